// round 2
// baseline (speedup 1.0000x reference)
#include <cuda_runtime.h>
#include <cuda_bf16.h>

#define B_ 16
#define C_ 256
#define H_ 56
#define W_ 56
#define G_ 4
#define PAD_ 5
#define PH_ 66
#define PW_ 66
#define TW_ 8

// Scratch (static device globals — no allocation at runtime).
__device__ ulonglong2 g_pk[B_ * PH_ * PW_ * G_];          // (sign, nonzero) per (b,py,px,g)
__device__ unsigned long long g_wbits[3][9][C_];          // weight sign bits [branch][tap][outch]
__device__ float g_params[3][4][C_];                      // [branch][{scale, cb-move1, alpha, move2}][outch]

// ---------------------------------------------------------------------------
// Pack activations: s bit = (x+bias > 0), nz bit = (x+bias != 0).
// Padded grid (5 on each side) stores (0,0) => zero padding handled for free.
// ---------------------------------------------------------------------------
__global__ void pack_kernel(const float* __restrict__ x, const float* __restrict__ bias) {
    int idx = blockIdx.x * blockDim.x + threadIdx.x;
    if (idx >= B_ * PH_ * PW_ * G_) return;
    int g = idx & 3;
    int t = idx >> 2;
    int px = t % PW_; t /= PW_;
    int py = t % PH_;
    int b  = t / PH_;
    int yy = py - PAD_, xx = px - PAD_;
    unsigned long long s = 0ull, nz = 0ull;
    if (yy >= 0 && yy < H_ && xx >= 0 && xx < W_) {
        const float* xp = x + (((size_t)b * C_ + g * 64) * H_ + yy) * W_ + xx;
        const float* bp = bias + g * 64;
        #pragma unroll
        for (int c = 0; c < 64; c++) {
            float v = xp[(size_t)c * (H_ * W_)] + bp[c];
            s  |= (unsigned long long)(v > 0.0f)  << c;
            nz |= (unsigned long long)(v != 0.0f) << c;
        }
    }
    g_pk[idx] = make_ulonglong2(s, nz);
}

// ---------------------------------------------------------------------------
// Weight prep: per (branch, outch): mean, mean|w|, packed sign bits per tap.
// 64 threads = one per input channel within the group.
// ---------------------------------------------------------------------------
__global__ void wprep_kernel(const float* __restrict__ w, const float* __restrict__ cb,
                             const float* __restrict__ mv1, const float* __restrict__ alpha,
                             const float* __restrict__ mv2) {
    int o  = blockIdx.x;   // 0..255
    int br = blockIdx.y;   // 0..2
    int c  = threadIdx.x;  // 0..63
    const float* wp = w + (((size_t)br * C_ + o) * 64 + c) * 9;
    float vals[9];
    float sum = 0.0f, asum = 0.0f;
    #pragma unroll
    for (int t = 0; t < 9; t++) { float v = wp[t]; vals[t] = v; sum += v; asum += fabsf(v); }

    __shared__ float s1[64], s2[64];
    s1[c] = sum; s2[c] = asum;
    __syncthreads();
    #pragma unroll
    for (int off = 32; off > 0; off >>= 1) {
        if (c < off) { s1[c] += s1[c + off]; s2[c] += s2[c + off]; }
        __syncthreads();
    }
    float mean = s1[0] * (1.0f / 576.0f);

    __shared__ unsigned int bits[9][2];
    #pragma unroll
    for (int t = 0; t < 9; t++) {
        unsigned bm = __ballot_sync(0xFFFFFFFFu, vals[t] > mean);
        if ((c & 31) == 0) bits[t][c >> 5] = bm;
    }
    __syncthreads();
    if (c < 9)
        g_wbits[br][c][o] = ((unsigned long long)bits[c][1] << 32) | (unsigned long long)bits[c][0];
    if (c == 0) {
        int i = br * C_ + o;
        g_params[br][0][o] = s2[0] * (1.0f / 576.0f);   // scale = mean|w|
        g_params[br][1][o] = cb[i] - mv1[i];            // fused conv-bias - move1
        g_params[br][2][o] = alpha[i];
        g_params[br][3][o] = mv2[i];
    }
}

// ---------------------------------------------------------------------------
// Main kernel: one block = (b, y, 8 x-positions), 256 threads = 256 out chans.
// XNOR-popcount for 3 branches + RPReLU + sum, then fused LayerNorm over C.
// ---------------------------------------------------------------------------
__global__ void __launch_bounds__(256, 2)
main_kernel(const float* __restrict__ gamma, const float* __restrict__ beta,
            float* __restrict__ out) {
    const int x0 = blockIdx.x * TW_;
    const int y  = blockIdx.y;
    const int b  = blockIdx.z;
    const int o  = threadIdx.x;
    const int g  = o >> 6;

    __shared__ ulonglong2 tile[7 * 18 * 4];   // 7 rows {-5,-3,-1,0,1,3,5} x 18 cols x 4 groups
    __shared__ int pzs[3][4][TW_];            // sum of popc(nz) over the 9 taps, per branch/group/x
    __shared__ float redbuf[TW_][256];
    __shared__ float stats[TW_][2];

    // ---- load tile (coalesced 16B loads from L2-resident packed buffer) ----
    const int rowoff[7] = {-5, -3, -1, 0, 1, 3, 5};
    for (int e = o; e < 7 * 18 * 4; e += 256) {
        int gg  = e & 3;
        int q   = e >> 2;
        int col = q % 18;
        int r   = q / 18;
        int py  = y + rowoff[r] + PAD_;   // always in [0,65]
        int px  = x0 + col;               // always in [0,65]
        tile[e] = g_pk[(((size_t)b * PH_ + py) * PW_ + px) * G_ + gg];
    }
    __syncthreads();

    // ---- per-(branch,group,x) sum of popc(nz) over 9 taps (shared by 64 chans) ----
    if (o < 96) {
        int br = o / 32, rem = o % 32;
        int gg = rem >> 3, p = rem & 7;
        int d = 2 * br + 1;
        int s = 0;
        #pragma unroll
        for (int ky = 0; ky < 3; ky++) {
            int ridx = 3 + (ky - 1) * (br + 1);   // row index in 7-row tile
            #pragma unroll
            for (int kx = 0; kx < 3; kx++) {
                int col = 5 + p + (kx - 1) * d;
                s += __popcll(tile[(ridx * 18 + col) * 4 + gg].y);
            }
        }
        pzs[br][gg][p] = s;
    }
    __syncthreads();

    // ---- XNOR-popcount conv, 3 branches, fused RPReLU ----
    float outv[TW_];
    {
        float m2s = g_params[0][3][o] + g_params[1][3][o] + g_params[2][3][o];
        #pragma unroll
        for (int p = 0; p < TW_; p++) outv[p] = m2s;
    }

    const ulonglong2* tg = tile + g;

    #pragma unroll
    for (int br = 0; br < 3; br++) {
        const int d = 2 * br + 1;
        unsigned long long wq[9];
        #pragma unroll
        for (int t = 0; t < 9; t++) wq[t] = g_wbits[br][t][o];
        const float scl = g_params[br][0][o];
        const float c0  = g_params[br][1][o];
        const float al  = g_params[br][2][o];
        #pragma unroll
        for (int p = 0; p < TW_; p++) {
            int dsum = 0;
            #pragma unroll
            for (int ky = 0; ky < 3; ky++) {
                const int ridx = 3 + (ky - 1) * (br + 1);
                #pragma unroll
                for (int kx = 0; kx < 3; kx++) {
                    const int col = 5 + p + (kx - 1) * d;
                    ulonglong2 v = tg[(ridx * 18 + col) * 4];
                    // nz & (s ^ w): single LOP3 per 32-bit half
                    dsum += __popcll(v.y & (v.x ^ wq[ky * 3 + kx]));
                }
            }
            int dot = pzs[br][g][p] - 2 * dsum;     // integer-exact +/-1 dot product
            float yv = scl * (float)dot + c0;
            yv = (yv >= 0.0f) ? yv : al * yv;       // RPReLU core
            outv[p] += yv;
        }
    }

    // ---- fused LayerNorm over channels (256 threads = 256 channels) ----
    #pragma unroll
    for (int p = 0; p < TW_; p++) redbuf[p][o] = outv[p];
    __syncthreads();
    {
        int wid = o >> 5, lane = o & 31;  // 8 warps, warp w reduces position w
        float s = 0.0f, sq = 0.0f;
        #pragma unroll
        for (int k = 0; k < 8; k++) {
            float v = redbuf[wid][lane + 32 * k];
            s += v; sq += v * v;
        }
        #pragma unroll
        for (int off = 16; off > 0; off >>= 1) {
            s  += __shfl_down_sync(0xFFFFFFFFu, s,  off);
            sq += __shfl_down_sync(0xFFFFFFFFu, sq, off);
        }
        if (lane == 0) {
            float mean = s * (1.0f / 256.0f);
            float var  = sq * (1.0f / 256.0f) - mean * mean;
            stats[wid][0] = mean;
            stats[wid][1] = rsqrtf(var + 1e-5f);
        }
    }
    __syncthreads();

    float gm = gamma[o], bt = beta[o];
    float res[TW_];
    #pragma unroll
    for (int p = 0; p < TW_; p++)
        res[p] = (outv[p] - stats[p][0]) * stats[p][1] * gm + bt;

    float4* op = (float4*)(out + (((size_t)b * C_ + o) * H_ + y) * W_ + x0);
    op[0] = make_float4(res[0], res[1], res[2], res[3]);
    op[1] = make_float4(res[4], res[5], res[6], res[7]);
}

// ---------------------------------------------------------------------------
extern "C" void kernel_launch(void* const* d_in, const int* in_sizes, int n_in,
                              void* d_out, int out_size) {
    const float* x     = (const float*)d_in[0];
    const float* bias  = (const float*)d_in[1];
    const float* w     = (const float*)d_in[2];
    const float* cb    = (const float*)d_in[3];
    const float* mv1   = (const float*)d_in[4];
    const float* alpha = (const float*)d_in[5];
    const float* mv2   = (const float*)d_in[6];
    const float* gamma = (const float*)d_in[7];
    const float* beta  = (const float*)d_in[8];
    float* out = (float*)d_out;

    const int npack = B_ * PH_ * PW_ * G_;
    pack_kernel<<<(npack + 255) / 256, 256>>>(x, bias);
    wprep_kernel<<<dim3(C_, 3), 64>>>(w, cb, mv1, alpha, mv2);
    main_kernel<<<dim3(W_ / TW_, H_, B_), 256>>>(gamma, beta, out);
}

// round 3
// speedup vs baseline: 1.0095x; 1.0095x over previous
#include <cuda_runtime.h>
#include <cuda_bf16.h>

#define B_ 16
#define C_ 256
#define H_ 56
#define W_ 56
#define G_ 4
#define PAD_ 5
#define PH_ 66
#define PW_ 66
#define TW_ 8

// Scratch (static device globals — no allocation at runtime).
__device__ ulonglong2 g_pk[B_ * PH_ * PW_ * G_];          // (sign, nonzero) per (b,py,px,g)
__device__ unsigned long long g_wbits[3][9][C_];          // weight sign bits [branch][tap][outch]
__device__ float g_params[3][4][C_];                      // [branch][{scale, cb-move1, alpha, move2}][outch]

// ---------------------------------------------------------------------------
// Pack activations (coalesced): block = (py, b), warp = one group, lanes =
// consecutive padded-x. For fixed channel c, the 32 lanes read 32 consecutive
// floats -> fully coalesced. Border positions write (0,0) = zero padding.
// ---------------------------------------------------------------------------
__global__ void pack_kernel(const float* __restrict__ x, const float* __restrict__ bias) {
    const int py   = blockIdx.x;
    const int b    = blockIdx.y;
    const int g    = threadIdx.x >> 5;     // 4 warps = 4 groups
    const int lane = threadIdx.x & 31;
    const int yy   = py - PAD_;
    const bool rowin = (yy >= 0) && (yy < H_);
    const float* bp = bias + g * 64;

    #pragma unroll
    for (int px0 = 0; px0 < PW_; px0 += 32) {
        int px = px0 + lane;
        int xx = px - PAD_;
        bool in = rowin && (xx >= 0) && (xx < W_) && (px < PW_);
        unsigned long long s = 0ull, nz = 0ull;
        if (in) {
            const float* xp = x + (((size_t)b * C_ + g * 64) * H_ + yy) * W_ + xx;
            #pragma unroll
            for (int c = 0; c < 64; c++) {
                float v = __ldg(xp + (size_t)c * (H_ * W_)) + __ldg(bp + c);
                s  |= (unsigned long long)(v > 0.0f)  << c;
                nz |= (unsigned long long)(v != 0.0f) << c;
            }
        }
        if (px < PW_)
            g_pk[(((size_t)b * PH_ + py) * PW_ + px) * G_ + g] = make_ulonglong2(s, nz);
    }
}

// ---------------------------------------------------------------------------
// Weight prep: per (branch, outch): mean, mean|w|, packed sign bits per tap.
// ---------------------------------------------------------------------------
__global__ void wprep_kernel(const float* __restrict__ w, const float* __restrict__ cb,
                             const float* __restrict__ mv1, const float* __restrict__ alpha,
                             const float* __restrict__ mv2) {
    int o  = blockIdx.x;   // 0..255
    int br = blockIdx.y;   // 0..2
    int c  = threadIdx.x;  // 0..63
    const float* wp = w + (((size_t)br * C_ + o) * 64 + c) * 9;
    float vals[9];
    float sum = 0.0f, asum = 0.0f;
    #pragma unroll
    for (int t = 0; t < 9; t++) { float v = wp[t]; vals[t] = v; sum += v; asum += fabsf(v); }

    __shared__ float s1[64], s2[64];
    s1[c] = sum; s2[c] = asum;
    __syncthreads();
    #pragma unroll
    for (int off = 32; off > 0; off >>= 1) {
        if (c < off) { s1[c] += s1[c + off]; s2[c] += s2[c + off]; }
        __syncthreads();
    }
    float mean = s1[0] * (1.0f / 576.0f);

    __shared__ unsigned int bits[9][2];
    #pragma unroll
    for (int t = 0; t < 9; t++) {
        unsigned bm = __ballot_sync(0xFFFFFFFFu, vals[t] > mean);
        if ((c & 31) == 0) bits[t][c >> 5] = bm;
    }
    __syncthreads();
    if (c < 9)
        g_wbits[br][c][o] = ((unsigned long long)bits[c][1] << 32) | (unsigned long long)bits[c][0];
    if (c == 0) {
        int i = br * C_ + o;
        g_params[br][0][o] = s2[0] * (1.0f / 576.0f);   // scale = mean|w|
        g_params[br][1][o] = cb[i] - mv1[i];            // fused conv-bias - move1
        g_params[br][2][o] = alpha[i];
        g_params[br][3][o] = mv2[i];
    }
}

// ---------------------------------------------------------------------------
// Main kernel: one block = (b, y, 8 x-positions), 128 threads; each thread
// computes TWO output channels of the same group (g*64+j and g*64+j+32) so
// every tile LDS feeds two XNOR-popcounts. Fused RPReLU + sum + LayerNorm.
// ---------------------------------------------------------------------------
__global__ void __launch_bounds__(128, 4)
main_kernel(const float* __restrict__ gamma, const float* __restrict__ beta,
            float* __restrict__ out) {
    const int x0 = blockIdx.x * TW_;
    const int y  = blockIdx.y;
    const int b  = blockIdx.z;
    const int t  = threadIdx.x;
    const int g  = t >> 5;               // 4 warps = 4 groups
    const int j  = t & 31;
    const int c0 = g * 64 + j;
    const int c1 = c0 + 32;

    __shared__ ulonglong2 tile[7 * 18 * 4];   // rows {-5,-3,-1,0,1,3,5} x 18 cols x 4 groups
    __shared__ int pzs[3][4][TW_];
    __shared__ float redbuf[TW_][256];
    __shared__ float stats[TW_][2];

    // ---- load tile ----
    const int rowoff[7] = {-5, -3, -1, 0, 1, 3, 5};
    for (int e = t; e < 7 * 18 * 4; e += 128) {
        int gg  = e & 3;
        int q   = e >> 2;
        int col = q % 18;
        int r   = q / 18;
        int py  = y + rowoff[r] + PAD_;
        int px  = x0 + col;
        tile[e] = g_pk[(((size_t)b * PH_ + py) * PW_ + px) * G_ + gg];
    }
    __syncthreads();

    // ---- per-(branch,group,x) sum of popc(nz) over 9 taps ----
    if (t < 96) {
        int br = t / 32, rem = t % 32;
        int gg = rem >> 3, p = rem & 7;
        int d = 2 * br + 1;
        int s = 0;
        #pragma unroll
        for (int ky = 0; ky < 3; ky++) {
            int ridx = 3 + (ky - 1) * (br + 1);
            #pragma unroll
            for (int kx = 0; kx < 3; kx++) {
                int col = 5 + p + (kx - 1) * d;
                s += __popcll(tile[(ridx * 18 + col) * 4 + gg].y);
            }
        }
        pzs[br][gg][p] = s;
    }
    __syncthreads();

    // ---- XNOR-popcount conv, 3 branches x 2 channels, fused RPReLU ----
    float outa[TW_], outb[TW_];
    {
        float m2a = g_params[0][3][c0] + g_params[1][3][c0] + g_params[2][3][c0];
        float m2b = g_params[0][3][c1] + g_params[1][3][c1] + g_params[2][3][c1];
        #pragma unroll
        for (int p = 0; p < TW_; p++) { outa[p] = m2a; outb[p] = m2b; }
    }

    const ulonglong2* tg = tile + g;

    #pragma unroll
    for (int br = 0; br < 3; br++) {
        const int d = 2 * br + 1;
        unsigned long long wa[9], wb[9];
        #pragma unroll
        for (int tt = 0; tt < 9; tt++) { wa[tt] = g_wbits[br][tt][c0]; wb[tt] = g_wbits[br][tt][c1]; }
        const float sa = g_params[br][0][c0], sb = g_params[br][0][c1];
        const float ka = g_params[br][1][c0], kb = g_params[br][1][c1];
        const float aa = g_params[br][2][c0], ab = g_params[br][2][c1];
        #pragma unroll
        for (int p = 0; p < TW_; p++) {
            int da = 0, db = 0;
            #pragma unroll
            for (int ky = 0; ky < 3; ky++) {
                const int ridx = 3 + (ky - 1) * (br + 1);
                #pragma unroll
                for (int kx = 0; kx < 3; kx++) {
                    const int col = 5 + p + (kx - 1) * d;
                    ulonglong2 v = tg[(ridx * 18 + col) * 4];  // one LDS feeds 2 channels
                    da += __popcll(v.y & (v.x ^ wa[ky * 3 + kx]));
                    db += __popcll(v.y & (v.x ^ wb[ky * 3 + kx]));
                }
            }
            int base = pzs[br][g][p];
            float ya = sa * (float)(base - 2 * da) + ka;
            float yb = sb * (float)(base - 2 * db) + kb;
            ya = (ya >= 0.0f) ? ya : aa * ya;
            yb = (yb >= 0.0f) ? yb : ab * yb;
            outa[p] += ya;
            outb[p] += yb;
        }
    }

    // ---- fused LayerNorm over channels ----
    #pragma unroll
    for (int p = 0; p < TW_; p++) { redbuf[p][c0] = outa[p]; redbuf[p][c1] = outb[p]; }
    __syncthreads();
    {
        int wid = t >> 5, lane = t & 31;   // 4 warps, warp w reduces positions 2w, 2w+1
        #pragma unroll
        for (int q = 0; q < 2; q++) {
            int p = wid * 2 + q;
            float s = 0.0f, sq = 0.0f;
            #pragma unroll
            for (int k = 0; k < 8; k++) {
                float v = redbuf[p][lane + 32 * k];
                s += v; sq += v * v;
            }
            #pragma unroll
            for (int off = 16; off > 0; off >>= 1) {
                s  += __shfl_down_sync(0xFFFFFFFFu, s,  off);
                sq += __shfl_down_sync(0xFFFFFFFFu, sq, off);
            }
            if (lane == 0) {
                float mean = s * (1.0f / 256.0f);
                float var  = sq * (1.0f / 256.0f) - mean * mean;
                stats[p][0] = mean;
                stats[p][1] = rsqrtf(var + 1e-5f);
            }
        }
    }
    __syncthreads();

    float g0 = gamma[c0], b0 = beta[c0];
    float g1 = gamma[c1], b1 = beta[c1];
    float ra[TW_], rb[TW_];
    #pragma unroll
    for (int p = 0; p < TW_; p++) {
        ra[p] = (outa[p] - stats[p][0]) * stats[p][1] * g0 + b0;
        rb[p] = (outb[p] - stats[p][0]) * stats[p][1] * g1 + b1;
    }

    float4* opa = (float4*)(out + (((size_t)b * C_ + c0) * H_ + y) * W_ + x0);
    float4* opb = (float4*)(out + (((size_t)b * C_ + c1) * H_ + y) * W_ + x0);
    opa[0] = make_float4(ra[0], ra[1], ra[2], ra[3]);
    opa[1] = make_float4(ra[4], ra[5], ra[6], ra[7]);
    opb[0] = make_float4(rb[0], rb[1], rb[2], rb[3]);
    opb[1] = make_float4(rb[4], rb[5], rb[6], rb[7]);
}

// ---------------------------------------------------------------------------
extern "C" void kernel_launch(void* const* d_in, const int* in_sizes, int n_in,
                              void* d_out, int out_size) {
    const float* x     = (const float*)d_in[0];
    const float* bias  = (const float*)d_in[1];
    const float* w     = (const float*)d_in[2];
    const float* cb    = (const float*)d_in[3];
    const float* mv1   = (const float*)d_in[4];
    const float* alpha = (const float*)d_in[5];
    const float* mv2   = (const float*)d_in[6];
    const float* gamma = (const float*)d_in[7];
    const float* beta  = (const float*)d_in[8];
    float* out = (float*)d_out;

    pack_kernel<<<dim3(PH_, B_), 128>>>(x, bias);
    wprep_kernel<<<dim3(C_, 3), 64>>>(w, cb, mv1, alpha, mv2);
    main_kernel<<<dim3(W_ / TW_, H_, B_), 128>>>(gamma, beta, out);
}